// round 2
// baseline (speedup 1.0000x reference)
#include <cuda_runtime.h>
#include <cstdint>

#define B_    32
#define T_    512
#define D_    512
#define H_    512
#define FOURH 2048
#define NCTA  64          // CTAs per direction

typedef unsigned long long ull;

// ---- scratch (static device memory is the only legal scratch) ----
__device__ float g_xp[2][(size_t)B_ * T_ * FOURH];   // input projections
__device__ float g_h[2][2][H_ * B_];                 // h state, TRANSPOSED [j][b], [dir][parity]
__device__ unsigned g_count[2];
__device__ unsigned g_gen[2];

__device__ __forceinline__ float sigm(float x) { return 1.f / (1.f + __expf(-x)); }
__device__ __forceinline__ float tanh_(float x) { return 2.f / (1.f + __expf(-2.f * x)) - 1.f; }

__device__ __forceinline__ ull fma2(ull a, ull b, ull c) {
    ull d;
    asm("fma.rn.f32x2 %0, %1, %2, %3;" : "=l"(d) : "l"(a), "l"(b), "l"(c));
    return d;
}
union F2U { ull u; float2 f; };
__device__ __forceinline__ float2 u2f(ull v) { F2U x; x.u = v; return x.f; }

// ---------------------------------------------------------------------------
// Phase 1: xp[dir] = x @ W[dir][:D] + b[dir]
// 128x128x8 tile, FFMA2 microkernel (8x8 per thread as 8x4 f32x2 pairs),
// duplicated-A smem ({a,a} pairs load directly), double-buffered, 1 sync/iter.
// ---------------------------------------------------------------------------
__global__ __launch_bounds__(256, 2) void gemm_xp(
    const float* __restrict__ x,
    const float* __restrict__ Wfw, const float* __restrict__ bfw,
    const float* __restrict__ Wbw, const float* __restrict__ bbw)
{
    const int dir = blockIdx.z;
    const float* __restrict__ Wd = dir ? Wbw : Wfw;
    const float* __restrict__ bd = dir ? bbw : bfw;
    float* __restrict__ C = g_xp[dir];

    __shared__ float As[2][8][256];   // duplicated: [k][2m], value stored twice
    __shared__ float Bs[2][8][128];

    const int tid = threadIdx.x;
    const int m0 = blockIdx.y * 128;
    const int n0 = blockIdx.x * 128;
    const int tx = tid & 15;
    const int ty = tid >> 4;

    const int arow = tid >> 1;
    const int ak4  = (tid & 1) * 4;
    const int bk = tid >> 5;
    const int bn = (tid & 31) * 4;

    const float* Ap = x  + (size_t)(m0 + arow) * D_ + ak4;
    const float* Bp = Wd + (size_t)bk * FOURH + n0 + bn;

    ull acc[8][4];
#pragma unroll
    for (int i = 0; i < 8; i++)
#pragma unroll
        for (int j = 0; j < 4; j++) acc[i][j] = 0ull;

    float4 av = *(const float4*)(Ap);
    float4 bv = *(const float4*)(Bp);

    for (int k0 = 0; k0 < D_; k0 += 8) {
        const int buf = (k0 >> 3) & 1;
        *(float2*)&As[buf][ak4 + 0][2 * arow] = make_float2(av.x, av.x);
        *(float2*)&As[buf][ak4 + 1][2 * arow] = make_float2(av.y, av.y);
        *(float2*)&As[buf][ak4 + 2][2 * arow] = make_float2(av.z, av.z);
        *(float2*)&As[buf][ak4 + 3][2 * arow] = make_float2(av.w, av.w);
        *(float4*)&Bs[buf][bk][bn] = bv;
        __syncthreads();

        if (k0 + 8 < D_) {
            av = *(const float4*)(Ap + k0 + 8);
            bv = *(const float4*)(Bp + (size_t)(k0 + 8) * FOURH);
        }

#pragma unroll
        for (int kk = 0; kk < 8; kk++) {
            const ulonglong2* ap2 = (const ulonglong2*)&As[buf][kk][ty * 16];
            const ulonglong2* bp2 = (const ulonglong2*)&Bs[buf][kk][tx * 8];
            ulonglong2 a01 = ap2[0], a23 = ap2[1], a45 = ap2[2], a67 = ap2[3];
            ulonglong2 b01 = bp2[0], b23 = bp2[1];
            ull aa[8] = {a01.x, a01.y, a23.x, a23.y, a45.x, a45.y, a67.x, a67.y};
            ull bb[4] = {b01.x, b01.y, b23.x, b23.y};
#pragma unroll
            for (int i = 0; i < 8; i++)
#pragma unroll
                for (int j = 0; j < 4; j++)
                    acc[i][j] = fma2(aa[i], bb[j], acc[i][j]);
        }
        // single sync per iteration: next store goes to the other buffer, and
        // re-store of this buffer is fenced by the NEXT iteration's sync.
    }
    __syncthreads();

    float bias[8];
#pragma unroll
    for (int j = 0; j < 8; j++) bias[j] = bd[n0 + tx * 8 + j];

#pragma unroll
    for (int i = 0; i < 8; i++) {
        const size_t row = (size_t)(m0 + ty * 8 + i);
        float* cp = C + row * FOURH + n0 + tx * 8;
        float2 c0 = u2f(acc[i][0]), c1 = u2f(acc[i][1]);
        float2 c2 = u2f(acc[i][2]), c3 = u2f(acc[i][3]);
        float4 o0, o1;
        o0.x = c0.x + bias[0]; o0.y = c0.y + bias[1];
        o0.z = c1.x + bias[2]; o0.w = c1.y + bias[3];
        o1.x = c2.x + bias[4]; o1.y = c2.y + bias[5];
        o1.z = c3.x + bias[6]; o1.w = c3.y + bias[7];
        *(float4*)(cp + 0) = o0;
        *(float4*)(cp + 4) = o1;
    }
}

// ---------------------------------------------------------------------------
// Phase 2: persistent bidirectional LSTM recurrence, FFMA2 matvec.
// 128 CTAs (64/dir), 256 threads, 1 CTA/SM (215KB smem).
// smem: Wsh [k][32 cols] transposed (64KB, resident all 512 steps)
//       hsh2 [k][2b] transposed + duplicated (128KB, restaged per step)
//       red  [4 ksplit][32 b][36] partial-z reduction buffer (18KB)
// Thread roles (matvec): ks=tid>>6, b4=(tid>>3)&7, c4=tid&7 — 4 batches x
// 4 cols per thread over 128 k's -> 3 LDS wavefronts per 8 FFMA2 (FMA-bound).
// Gate stage: b_g=tid>>3, jj_g=tid&7 as before.
// ---------------------------------------------------------------------------
#define W_FLOATS   (512 * 32)          // 16384
#define H2_FLOATS  (512 * 64)          // 32768
#define RED_STRIDE 36
#define RED(ks, b, c) ((((ks) * 32 + (b)) * RED_STRIDE) + (c))
#define SMEM_BYTES ((W_FLOATS + H2_FLOATS + 4 * 32 * RED_STRIDE) * 4)

__global__ __launch_bounds__(256) void lstm_kernel(
    const float* __restrict__ Wfw, const float* __restrict__ Wbw,
    float* __restrict__ out)
{
    extern __shared__ float sm[];
    float* Wsh  = sm;                        // [k][c] : k*32 + c
    float* hsh2 = sm + W_FLOATS;             // [k][2b]: k*64 + 2b (duplicated)
    float* red  = sm + W_FLOATS + H2_FLOATS; // [ks][b][36]

    const int tid = threadIdx.x;
    const int dir = blockIdx.x / NCTA;
    const int cta = blockIdx.x % NCTA;
    const int j0  = cta * 8;
    const float* __restrict__ W  = dir ? Wbw : Wfw;
    const float* __restrict__ xp = g_xp[dir];

    // Prologue: Wh slice -> smem transposed [k][c], c = gate*8 + jj.
    for (int idx = tid; idx < W_FLOATS; idx += 256) {
        const int k = idx >> 5, c = idx & 31;
        const int gate = c >> 3, jj = c & 7;
        Wsh[k * 32 + c] = W[(size_t)(D_ + k) * FOURH + gate * H_ + j0 + jj];
    }

    // matvec roles
    const int ks = tid >> 6;                 // k-split 0..3
    const int b4 = (tid >> 3) & 7;           // batch group (4 batches)
    const int c4 = tid & 7;                  // col group (4 cols)
    // gate roles
    const int b_g = tid >> 3, jj_g = tid & 7;

    float cst = 0.f;
    __syncthreads();

    for (int s = 0; s < T_; s++) {
        const int t = dir ? (T_ - 1 - s) : s;

        // issue xp loads early (independent of everything this step)
        const size_t xrow = ((size_t)b_g * T_ + t) * FOURH + j0 + jj_g;
        float x0 = __ldg(xp + xrow + 0 * H_);
        float x1 = __ldg(xp + xrow + 1 * H_);
        float x2 = __ldg(xp + xrow + 2 * H_);
        float x3 = __ldg(xp + xrow + 3 * H_);

        if (s > 0) {
            // stage h (transposed [j][b] in gmem) -> hsh2 [k][2b] duplicated
            const float2* src = (const float2*)(g_h[dir][(s - 1) & 1]);
#pragma unroll 4
            for (int i = tid; i < (H_ * B_) / 2; i += 256) {
                float2 v = __ldcg(src + i);
                const int j = i >> 4, b2 = i & 15;
                *(float4*)(hsh2 + j * 64 + 4 * b2) =
                    make_float4(v.x, v.x, v.y, v.y);
            }
        }
        __syncthreads();

        if (s > 0) {
            ull a00 = 0, a01 = 0, a10 = 0, a11 = 0;
            ull a20 = 0, a21 = 0, a30 = 0, a31 = 0;
            const float* hbase = hsh2 + (size_t)ks * 128 * 64 + 8 * b4;
            const float* wbase = Wsh  + (size_t)ks * 128 * 32 + 4 * c4;
#pragma unroll 4
            for (int k = 0; k < 128; k++) {
                ulonglong2 hA = *(const ulonglong2*)(hbase + k * 64);
                ulonglong2 hB = *(const ulonglong2*)(hbase + k * 64 + 4);
                ulonglong2 wv = *(const ulonglong2*)(wbase + k * 32);
                a00 = fma2(hA.x, wv.x, a00); a01 = fma2(hA.x, wv.y, a01);
                a10 = fma2(hA.y, wv.x, a10); a11 = fma2(hA.y, wv.y, a11);
                a20 = fma2(hB.x, wv.x, a20); a21 = fma2(hB.x, wv.y, a21);
                a30 = fma2(hB.y, wv.x, a30); a31 = fma2(hB.y, wv.y, a31);
            }
            // write partials: red[ks][4*b4+bi][4*c4 .. +3]
            float2 p;
            p = u2f(a00); float2 q = u2f(a01);
            *(float4*)&red[RED(ks, 4 * b4 + 0, 4 * c4)] = make_float4(p.x, p.y, q.x, q.y);
            p = u2f(a10); q = u2f(a11);
            *(float4*)&red[RED(ks, 4 * b4 + 1, 4 * c4)] = make_float4(p.x, p.y, q.x, q.y);
            p = u2f(a20); q = u2f(a21);
            *(float4*)&red[RED(ks, 4 * b4 + 2, 4 * c4)] = make_float4(p.x, p.y, q.x, q.y);
            p = u2f(a30); q = u2f(a31);
            *(float4*)&red[RED(ks, 4 * b4 + 3, 4 * c4)] = make_float4(p.x, p.y, q.x, q.y);
        }
        __syncthreads();

        // gate stage: z = sum_ks red + xp
        float z0 = x0, z1 = x1, z2 = x2, z3 = x3;
        if (s > 0) {
#pragma unroll
            for (int kk = 0; kk < 4; kk++) {
                z0 += red[RED(kk, b_g,  0 + jj_g)];
                z1 += red[RED(kk, b_g,  8 + jj_g)];
                z2 += red[RED(kk, b_g, 16 + jj_g)];
                z3 += red[RED(kk, b_g, 24 + jj_g)];
            }
        }
        const float ig = sigm(z0), fg = sigm(z1), og = sigm(z2), gg = tanh_(z3);
        cst = fmaf(fg, cst, ig * gg);
        const float hv = og * tanh_(cst);

        const int j = j0 + jj_g;
        __stcg(&g_h[dir][s & 1][j * B_ + b_g], hv);                 // transposed
        out[((size_t)b_g * T_ + t) * (2 * H_) + dir * H_ + j] = hv; // final output

        // per-direction grid barrier (sense-reversing)
        if (tid == 0) {
            __threadfence();
            const unsigned gen = *(volatile unsigned*)&g_gen[dir];
            const unsigned old = atomicAdd(&g_count[dir], 1);
            if (old == NCTA - 1) {
                atomicExch(&g_count[dir], 0);
                __threadfence();
                atomicAdd(&g_gen[dir], 1);
            } else {
                while (*(volatile unsigned*)&g_gen[dir] == gen) { }
            }
            __threadfence();
        }
        __syncthreads();
    }
}

// ---------------------------------------------------------------------------
extern "C" void kernel_launch(void* const* d_in, const int* in_sizes, int n_in,
                              void* d_out, int out_size)
{
    const float* x   = (const float*)d_in[0];
    const float* Wfw = (const float*)d_in[1];
    const float* bfw = (const float*)d_in[2];
    const float* Wbw = (const float*)d_in[3];
    const float* bbw = (const float*)d_in[4];
    float* out = (float*)d_out;

    dim3 g(FOURH / 128, (B_ * T_) / 128, 2);
    gemm_xp<<<g, 256>>>(x, Wfw, bfw, Wbw, bbw);

    cudaFuncSetAttribute(lstm_kernel,
                         cudaFuncAttributeMaxDynamicSharedMemorySize, SMEM_BYTES);
    lstm_kernel<<<2 * NCTA, 256, SMEM_BYTES>>>(Wfw, Wbw, out);
}

// round 4
// speedup vs baseline: 1.1770x; 1.1770x over previous
#include <cuda_runtime.h>
#include <cstdint>

#define B_    32
#define T_    512
#define D_    512
#define H_    512
#define FOURH 2048
#define NCTA  64          // CTAs per direction

typedef unsigned long long ull;

// ---- scratch ----
__device__ float g_xp[2][(size_t)B_ * T_ * FOURH];   // input projections
__device__ float g_h[2][2][H_ * B_];                 // h state, TRANSPOSED [j][b]
__device__ unsigned g_count[2];
__device__ unsigned g_gen[2];

__device__ __forceinline__ float sigm(float x) { return 1.f / (1.f + __expf(-x)); }
__device__ __forceinline__ float tanh_(float x) { return 2.f / (1.f + __expf(-2.f * x)) - 1.f; }

__device__ __forceinline__ ull fma2(ull a, ull b, ull c) {
    ull d;
    asm("fma.rn.f32x2 %0, %1, %2, %3;" : "=l"(d) : "l"(a), "l"(b), "l"(c));
    return d;
}
union F2U { ull u; float2 f; };
__device__ __forceinline__ float2 u2f(ull v) { F2U x; x.u = v; return x.f; }

// ---------------------------------------------------------------------------
// Phase 1: xp GEMM — unchanged (controlled variable this round).
// ---------------------------------------------------------------------------
__global__ __launch_bounds__(256, 2) void gemm_xp(
    const float* __restrict__ x,
    const float* __restrict__ Wfw, const float* __restrict__ bfw,
    const float* __restrict__ Wbw, const float* __restrict__ bbw)
{
    const int dir = blockIdx.z;
    const float* __restrict__ Wd = dir ? Wbw : Wfw;
    const float* __restrict__ bd = dir ? bbw : bfw;
    float* __restrict__ C = g_xp[dir];

    __shared__ float As[2][8][256];
    __shared__ float Bs[2][8][128];

    const int tid = threadIdx.x;
    const int m0 = blockIdx.y * 128;
    const int n0 = blockIdx.x * 128;
    const int tx = tid & 15;
    const int ty = tid >> 4;

    const int arow = tid >> 1;
    const int ak4  = (tid & 1) * 4;
    const int bk = tid >> 5;
    const int bn = (tid & 31) * 4;

    const float* Ap = x  + (size_t)(m0 + arow) * D_ + ak4;
    const float* Bp = Wd + (size_t)bk * FOURH + n0 + bn;

    ull acc[8][4];
#pragma unroll
    for (int i = 0; i < 8; i++)
#pragma unroll
        for (int j = 0; j < 4; j++) acc[i][j] = 0ull;

    float4 av = *(const float4*)(Ap);
    float4 bv = *(const float4*)(Bp);

    for (int k0 = 0; k0 < D_; k0 += 8) {
        const int buf = (k0 >> 3) & 1;
        *(float2*)&As[buf][ak4 + 0][2 * arow] = make_float2(av.x, av.x);
        *(float2*)&As[buf][ak4 + 1][2 * arow] = make_float2(av.y, av.y);
        *(float2*)&As[buf][ak4 + 2][2 * arow] = make_float2(av.z, av.z);
        *(float2*)&As[buf][ak4 + 3][2 * arow] = make_float2(av.w, av.w);
        *(float4*)&Bs[buf][bk][bn] = bv;
        __syncthreads();

        if (k0 + 8 < D_) {
            av = *(const float4*)(Ap + k0 + 8);
            bv = *(const float4*)(Bp + (size_t)(k0 + 8) * FOURH);
        }

#pragma unroll
        for (int kk = 0; kk < 8; kk++) {
            const ulonglong2* ap2 = (const ulonglong2*)&As[buf][kk][ty * 16];
            const ulonglong2* bp2 = (const ulonglong2*)&Bs[buf][kk][tx * 8];
            ulonglong2 a01 = ap2[0], a23 = ap2[1], a45 = ap2[2], a67 = ap2[3];
            ulonglong2 b01 = bp2[0], b23 = bp2[1];
            ull aa[8] = {a01.x, a01.y, a23.x, a23.y, a45.x, a45.y, a67.x, a67.y};
            ull bb[4] = {b01.x, b01.y, b23.x, b23.y};
#pragma unroll
            for (int i = 0; i < 8; i++)
#pragma unroll
                for (int j = 0; j < 4; j++)
                    acc[i][j] = fma2(aa[i], bb[j], acc[i][j]);
        }
    }
    __syncthreads();

    float bias[8];
#pragma unroll
    for (int j = 0; j < 8; j++) bias[j] = bd[n0 + tx * 8 + j];

#pragma unroll
    for (int i = 0; i < 8; i++) {
        const size_t row = (size_t)(m0 + ty * 8 + i);
        float* cp = C + row * FOURH + n0 + tx * 8;
        float2 c0 = u2f(acc[i][0]), c1 = u2f(acc[i][1]);
        float2 c2 = u2f(acc[i][2]), c3 = u2f(acc[i][3]);
        float4 o0, o1;
        o0.x = c0.x + bias[0]; o0.y = c0.y + bias[1];
        o0.z = c1.x + bias[2]; o0.w = c1.y + bias[3];
        o1.x = c2.x + bias[4]; o1.y = c2.y + bias[5];
        o1.z = c3.x + bias[6]; o1.w = c3.y + bias[7];
        *(float4*)(cp + 0) = o0;
        *(float4*)(cp + 4) = o1;
    }
}

// ---------------------------------------------------------------------------
// Phase 2: persistent LSTM, 512 threads/CTA (16 warps).
// smem: Wsh 64KB resident, hsh2 128KB (restaged per step),
//       red [8][32][34] = 34KB. Total 231,424 B <= 232,448 ceiling.
// RED_STRIDE=34: even (float2-aligned partial stores), 34%32=2 skews banks.
// ---------------------------------------------------------------------------
#define W_FLOATS   (512 * 32)
#define H2_FLOATS  (512 * 64)
#define RED_STRIDE 34
#define NSPLIT     8
#define RED(ks, b, c) ((((ks) * 32 + (b)) * RED_STRIDE) + (c))
#define SMEM_BYTES ((W_FLOATS + H2_FLOATS + NSPLIT * 32 * RED_STRIDE) * 4)

__global__ __launch_bounds__(512) void lstm_kernel(
    const float* __restrict__ Wfw, const float* __restrict__ Wbw,
    float* __restrict__ out)
{
    extern __shared__ float sm[];
    float* Wsh  = sm;                        // [k][c]
    float* hsh2 = sm + W_FLOATS;             // [k][2b] duplicated
    float* red  = sm + W_FLOATS + H2_FLOATS; // [ks][b][34]

    const int tid = threadIdx.x;
    const int dir = blockIdx.x / NCTA;
    const int cta = blockIdx.x % NCTA;
    const int j0  = cta * 8;
    const float* __restrict__ W  = dir ? Wbw : Wfw;
    const float* __restrict__ xp = g_xp[dir];

    // Prologue: Wh slice -> smem [k][c], c = gate*8 + jj.
    for (int idx = tid; idx < W_FLOATS; idx += 512) {
        const int k = idx >> 5, c = idx & 31;
        const int gate = c >> 3, jj = c & 7;
        Wsh[k * 32 + c] = W[(size_t)(D_ + k) * FOURH + gate * H_ + j0 + jj];
    }

    // matvec roles
    const int ks = tid >> 6;                 // 0..7 (8 splits of 64 k)
    const int b4 = (tid >> 3) & 7;
    const int c4 = tid & 7;
    // gate roles (first 256 threads only)
    const int b_g = tid >> 3, jj_g = tid & 7;
    const bool gate_thread = (tid < 256);

    float cst = 0.f;
    __syncthreads();

    for (int s = 0; s < T_; s++) {
        const int t = dir ? (T_ - 1 - s) : s;

        float x0 = 0, x1 = 0, x2 = 0, x3 = 0;
        if (gate_thread) {
            const size_t xrow = ((size_t)b_g * T_ + t) * FOURH + j0 + jj_g;
            x0 = __ldg(xp + xrow + 0 * H_);
            x1 = __ldg(xp + xrow + 1 * H_);
            x2 = __ldg(xp + xrow + 2 * H_);
            x3 = __ldg(xp + xrow + 3 * H_);
        }

        if (s > 0) {
            // stage h ([j][b] in gmem) -> hsh2 [k][2b] duplicated
            const float2* src = (const float2*)(g_h[dir][(s - 1) & 1]);
#pragma unroll 4
            for (int i = tid; i < (H_ * B_) / 2; i += 512) {
                float2 v = __ldcg(src + i);
                const int j = i >> 4, b2 = i & 15;
                *(float4*)(hsh2 + j * 64 + 4 * b2) =
                    make_float4(v.x, v.x, v.y, v.y);
            }
        }
        __syncthreads();

        if (s > 0) {
            ull a00 = 0, a01 = 0, a10 = 0, a11 = 0;
            ull a20 = 0, a21 = 0, a30 = 0, a31 = 0;
            const float* hbase = hsh2 + (size_t)ks * 64 * 64 + 8 * b4;
            const float* wbase = Wsh  + (size_t)ks * 64 * 32 + 4 * c4;
#pragma unroll 8
            for (int k = 0; k < 64; k++) {
                ulonglong2 hA = *(const ulonglong2*)(hbase + k * 64);
                ulonglong2 hB = *(const ulonglong2*)(hbase + k * 64 + 4);
                ulonglong2 wv = *(const ulonglong2*)(wbase + k * 32);
                a00 = fma2(hA.x, wv.x, a00); a01 = fma2(hA.x, wv.y, a01);
                a10 = fma2(hA.y, wv.x, a10); a11 = fma2(hA.y, wv.y, a11);
                a20 = fma2(hB.x, wv.x, a20); a21 = fma2(hB.x, wv.y, a21);
                a30 = fma2(hB.y, wv.x, a30); a31 = fma2(hB.y, wv.y, a31);
            }
            // partial stores as aligned float2 pairs (stride 34 = even)
            const int r0 = RED(ks, 4 * b4 + 0, 4 * c4);
            const int r1 = RED(ks, 4 * b4 + 1, 4 * c4);
            const int r2 = RED(ks, 4 * b4 + 2, 4 * c4);
            const int r3 = RED(ks, 4 * b4 + 3, 4 * c4);
            *(float2*)&red[r0]     = u2f(a00);
            *(float2*)&red[r0 + 2] = u2f(a01);
            *(float2*)&red[r1]     = u2f(a10);
            *(float2*)&red[r1 + 2] = u2f(a11);
            *(float2*)&red[r2]     = u2f(a20);
            *(float2*)&red[r2 + 2] = u2f(a21);
            *(float2*)&red[r3]     = u2f(a30);
            *(float2*)&red[r3 + 2] = u2f(a31);
        }
        __syncthreads();

        if (gate_thread) {
            float z0 = x0, z1 = x1, z2 = x2, z3 = x3;
            if (s > 0) {
#pragma unroll
                for (int kk = 0; kk < NSPLIT; kk++) {
                    z0 += red[RED(kk, b_g,  0 + jj_g)];
                    z1 += red[RED(kk, b_g,  8 + jj_g)];
                    z2 += red[RED(kk, b_g, 16 + jj_g)];
                    z3 += red[RED(kk, b_g, 24 + jj_g)];
                }
            }
            const float ig = sigm(z0), fg = sigm(z1), og = sigm(z2), gg = tanh_(z3);
            cst = fmaf(fg, cst, ig * gg);
            const float hv = og * tanh_(cst);

            const int j = j0 + jj_g;
            __stcg(&g_h[dir][s & 1][j * B_ + b_g], hv);
            out[((size_t)b_g * T_ + t) * (2 * H_) + dir * H_ + j] = hv;
        }

        // collect ALL threads' h-stores BEFORE publishing
        __syncthreads();

        if (tid == 0) {
            __threadfence();
            const unsigned gen = *(volatile unsigned*)&g_gen[dir];
            const unsigned old = atomicAdd(&g_count[dir], 1);
            if (old == NCTA - 1) {
                atomicExch(&g_count[dir], 0);
                __threadfence();
                atomicAdd(&g_gen[dir], 1);
            } else {
                while (*(volatile unsigned*)&g_gen[dir] == gen) { }
            }
            __threadfence();
        }
        __syncthreads();
    }
}

// ---------------------------------------------------------------------------
extern "C" void kernel_launch(void* const* d_in, const int* in_sizes, int n_in,
                              void* d_out, int out_size)
{
    const float* x   = (const float*)d_in[0];
    const float* Wfw = (const float*)d_in[1];
    const float* bfw = (const float*)d_in[2];
    const float* Wbw = (const float*)d_in[3];
    const float* bbw = (const float*)d_in[4];
    float* out = (float*)d_out;

    dim3 g(FOURH / 128, (B_ * T_) / 128, 2);
    gemm_xp<<<g, 256>>>(x, Wfw, bfw, Wbw, bbw);

    cudaFuncSetAttribute(lstm_kernel,
                         cudaFuncAttributeMaxDynamicSharedMemorySize, SMEM_BYTES);
    lstm_kernel<<<2 * NCTA, 512, SMEM_BYTES>>>(Wfw, Wbw, out);
}

// round 5
// speedup vs baseline: 1.2125x; 1.0302x over previous
#include <cuda_runtime.h>
#include <cstdint>

#define B_    32
#define T_    512
#define D_    512
#define H_    512
#define FOURH 2048
#define NCTA  64          // CTAs per direction

typedef unsigned long long ull;

// ---- scratch ----
__device__ float g_xp[2][(size_t)B_ * T_ * FOURH];   // input projections
__device__ float g_h[2][2][H_ * B_];                 // h state, TRANSPOSED [j][b]
__device__ unsigned g_count[2];
__device__ unsigned g_gen[2];

__device__ __forceinline__ float sigm(float x) { return 1.f / (1.f + __expf(-x)); }
__device__ __forceinline__ float tanh_(float x) { return 2.f / (1.f + __expf(-2.f * x)) - 1.f; }

__device__ __forceinline__ ull fma2(ull a, ull b, ull c) {
    ull d;
    asm("fma.rn.f32x2 %0, %1, %2, %3;" : "=l"(d) : "l"(a), "l"(b), "l"(c));
    return d;
}
union F2U { ull u; float2 f; };
__device__ __forceinline__ float2 u2f(ull v) { F2U x; x.u = v; return x.f; }

// ---------------------------------------------------------------------------
// Phase 1: xp GEMM — unchanged (controlled variable this round).
// ---------------------------------------------------------------------------
__global__ __launch_bounds__(256, 2) void gemm_xp(
    const float* __restrict__ x,
    const float* __restrict__ Wfw, const float* __restrict__ bfw,
    const float* __restrict__ Wbw, const float* __restrict__ bbw)
{
    const int dir = blockIdx.z;
    const float* __restrict__ Wd = dir ? Wbw : Wfw;
    const float* __restrict__ bd = dir ? bbw : bfw;
    float* __restrict__ C = g_xp[dir];

    __shared__ float As[2][8][256];
    __shared__ float Bs[2][8][128];

    const int tid = threadIdx.x;
    const int m0 = blockIdx.y * 128;
    const int n0 = blockIdx.x * 128;
    const int tx = tid & 15;
    const int ty = tid >> 4;

    const int arow = tid >> 1;
    const int ak4  = (tid & 1) * 4;
    const int bk = tid >> 5;
    const int bn = (tid & 31) * 4;

    const float* Ap = x  + (size_t)(m0 + arow) * D_ + ak4;
    const float* Bp = Wd + (size_t)bk * FOURH + n0 + bn;

    ull acc[8][4];
#pragma unroll
    for (int i = 0; i < 8; i++)
#pragma unroll
        for (int j = 0; j < 4; j++) acc[i][j] = 0ull;

    float4 av = *(const float4*)(Ap);
    float4 bv = *(const float4*)(Bp);

    for (int k0 = 0; k0 < D_; k0 += 8) {
        const int buf = (k0 >> 3) & 1;
        *(float2*)&As[buf][ak4 + 0][2 * arow] = make_float2(av.x, av.x);
        *(float2*)&As[buf][ak4 + 1][2 * arow] = make_float2(av.y, av.y);
        *(float2*)&As[buf][ak4 + 2][2 * arow] = make_float2(av.z, av.z);
        *(float2*)&As[buf][ak4 + 3][2 * arow] = make_float2(av.w, av.w);
        *(float4*)&Bs[buf][bk][bn] = bv;
        __syncthreads();

        if (k0 + 8 < D_) {
            av = *(const float4*)(Ap + k0 + 8);
            bv = *(const float4*)(Bp + (size_t)(k0 + 8) * FOURH);
        }

#pragma unroll
        for (int kk = 0; kk < 8; kk++) {
            const ulonglong2* ap2 = (const ulonglong2*)&As[buf][kk][ty * 16];
            const ulonglong2* bp2 = (const ulonglong2*)&Bs[buf][kk][tx * 8];
            ulonglong2 a01 = ap2[0], a23 = ap2[1], a45 = ap2[2], a67 = ap2[3];
            ulonglong2 b01 = bp2[0], b23 = bp2[1];
            ull aa[8] = {a01.x, a01.y, a23.x, a23.y, a45.x, a45.y, a67.x, a67.y};
            ull bb[4] = {b01.x, b01.y, b23.x, b23.y};
#pragma unroll
            for (int i = 0; i < 8; i++)
#pragma unroll
                for (int j = 0; j < 4; j++)
                    acc[i][j] = fma2(aa[i], bb[j], acc[i][j]);
        }
    }
    __syncthreads();

    float bias[8];
#pragma unroll
    for (int j = 0; j < 8; j++) bias[j] = bd[n0 + tx * 8 + j];

#pragma unroll
    for (int i = 0; i < 8; i++) {
        const size_t row = (size_t)(m0 + ty * 8 + i);
        float* cp = C + row * FOURH + n0 + tx * 8;
        float2 c0 = u2f(acc[i][0]), c1 = u2f(acc[i][1]);
        float2 c2 = u2f(acc[i][2]), c3 = u2f(acc[i][3]);
        float4 o0, o1;
        o0.x = c0.x + bias[0]; o0.y = c0.y + bias[1];
        o0.z = c1.x + bias[2]; o0.w = c1.y + bias[3];
        o1.x = c2.x + bias[4]; o1.y = c2.y + bias[5];
        o1.z = c3.x + bias[6]; o1.w = c3.y + bias[7];
        *(float4*)(cp + 0) = o0;
        *(float4*)(cp + 4) = o1;
    }
}

// ---------------------------------------------------------------------------
// Phase 2: persistent LSTM, 512 threads, W-duplicated / h-natural matvec.
// smem: Wsh2 [k][{w,w} x 32c] 128KB (dup ONCE in prologue, resident)
//       hsh  [k][32b] 64KB natural (plain copy per step, half the bytes)
//       red  [8 ks][32 c][34] 34KB
// matvec thread tile: 4 b x 4 c x 64 k. Per k per warp: 3 LDS.128, each
// <=128B distinct -> 1 crossbar wavefront each. FFMA2 pairs over BATCHES.
// Per-SM step: crossbar ~3072 cyc < FFMA2 floor 4096 -> FMA-bound.
// ---------------------------------------------------------------------------
#define W2_FLOATS  (512 * 64)          // 32768 (duplicated W)
#define H_FLOATS   (512 * 32)          // 16384
#define RED_STRIDE 34
#define NSPLIT     8
#define REDC(ks, c, b) ((((ks) * 32 + (c)) * RED_STRIDE) + (b))
#define SMEM_BYTES ((W2_FLOATS + H_FLOATS + NSPLIT * 32 * RED_STRIDE) * 4)

__global__ __launch_bounds__(512) void lstm_kernel(
    const float* __restrict__ Wfw, const float* __restrict__ Wbw,
    float* __restrict__ out)
{
    extern __shared__ float sm[];
    float* Wsh2 = sm;                         // [k][64] : k*64 + 2c (+0,+1 dup)
    float* hsh  = sm + W2_FLOATS;             // [k][32] : k*32 + b
    float* red  = sm + W2_FLOATS + H_FLOATS;  // [ks][c][34]

    const int tid = threadIdx.x;
    const int dir = blockIdx.x / NCTA;
    const int cta = blockIdx.x % NCTA;
    const int j0  = cta * 8;
    const float* __restrict__ W  = dir ? Wbw : Wfw;
    const float* __restrict__ xp = g_xp[dir];

    // Prologue: Wh slice -> smem duplicated pairs. c = gate*8 + jj.
    for (int idx = tid; idx < H_FLOATS; idx += 512) {
        const int k = idx >> 5, c = idx & 31;
        const int gate = c >> 3, jj = c & 7;
        const float v = W[(size_t)(D_ + k) * FOURH + gate * H_ + j0 + jj];
        Wsh2[k * 64 + 2 * c]     = v;
        Wsh2[k * 64 + 2 * c + 1] = v;
    }

    // matvec roles: tid = ks*64 + cg*8 + bq
    const int bq = tid & 7;                  // batch quad (4 batches)
    const int cg = (tid >> 3) & 7;           // col quad (4 cols)
    const int ks = tid >> 6;                 // k-split 0..7 (64 k each)
    // gate roles (first 256 threads)
    const int b_g = tid >> 3, jj_g = tid & 7;
    const bool gate_thread = (tid < 256);

    float cst = 0.f;
    __syncthreads();

    for (int s = 0; s < T_; s++) {
        const int t = dir ? (T_ - 1 - s) : s;

        float x0 = 0, x1 = 0, x2 = 0, x3 = 0;
        if (gate_thread) {
            const size_t xrow = ((size_t)b_g * T_ + t) * FOURH + j0 + jj_g;
            x0 = __ldg(xp + xrow + 0 * H_);
            x1 = __ldg(xp + xrow + 1 * H_);
            x2 = __ldg(xp + xrow + 2 * H_);
            x3 = __ldg(xp + xrow + 3 * H_);
        }

        if (s > 0) {
            // plain copy: g_h [j][b] -> hsh [k][b] (identical layout)
            const float4* src = (const float4*)(g_h[dir][(s - 1) & 1]);
            float4* dst = (float4*)hsh;
#pragma unroll 2
            for (int i = tid; i < H_FLOATS / 4; i += 512)
                dst[i] = __ldcg(src + i);
        }
        __syncthreads();

        if (s > 0) {
            ull a00 = 0, a01 = 0, a02 = 0, a03 = 0;
            ull a10 = 0, a11 = 0, a12 = 0, a13 = 0;
            const float* hbase = hsh  + ks * 64 * 32 + 4 * bq;
            const float* wbase = Wsh2 + ks * 64 * 64 + 8 * cg;
#pragma unroll 8
            for (int k = 0; k < 64; k++) {
                ulonglong2 hv = *(const ulonglong2*)(hbase + k * 32);
                ulonglong2 w0 = *(const ulonglong2*)(wbase + k * 64);
                ulonglong2 w1 = *(const ulonglong2*)(wbase + k * 64 + 4);
                a00 = fma2(hv.x, w0.x, a00); a01 = fma2(hv.x, w0.y, a01);
                a02 = fma2(hv.x, w1.x, a02); a03 = fma2(hv.x, w1.y, a03);
                a10 = fma2(hv.y, w0.x, a10); a11 = fma2(hv.y, w0.y, a11);
                a12 = fma2(hv.y, w1.x, a12); a13 = fma2(hv.y, w1.y, a13);
            }
            // red[ks][c][b]: pair over batches -> float2 at b = 4bq + 2bp
            const int c0 = cg * 4;
            const int bb = 4 * bq;
            *(float2*)&red[REDC(ks, c0 + 0, bb)]     = u2f(a00);
            *(float2*)&red[REDC(ks, c0 + 1, bb)]     = u2f(a01);
            *(float2*)&red[REDC(ks, c0 + 2, bb)]     = u2f(a02);
            *(float2*)&red[REDC(ks, c0 + 3, bb)]     = u2f(a03);
            *(float2*)&red[REDC(ks, c0 + 0, bb + 2)] = u2f(a10);
            *(float2*)&red[REDC(ks, c0 + 1, bb + 2)] = u2f(a11);
            *(float2*)&red[REDC(ks, c0 + 2, bb + 2)] = u2f(a12);
            *(float2*)&red[REDC(ks, c0 + 3, bb + 2)] = u2f(a13);
        }
        __syncthreads();

        if (gate_thread) {
            float z0 = x0, z1 = x1, z2 = x2, z3 = x3;
            if (s > 0) {
#pragma unroll
                for (int kk = 0; kk < NSPLIT; kk++) {
                    z0 += red[REDC(kk,  0 + jj_g, b_g)];
                    z1 += red[REDC(kk,  8 + jj_g, b_g)];
                    z2 += red[REDC(kk, 16 + jj_g, b_g)];
                    z3 += red[REDC(kk, 24 + jj_g, b_g)];
                }
            }
            const float ig = sigm(z0), fg = sigm(z1), og = sigm(z2), gg = tanh_(z3);
            cst = fmaf(fg, cst, ig * gg);
            const float hv = og * tanh_(cst);

            const int j = j0 + jj_g;
            __stcg(&g_h[dir][s & 1][j * B_ + b_g], hv);
            out[((size_t)b_g * T_ + t) * (2 * H_) + dir * H_ + j] = hv;
        }

        // collect ALL threads' h-stores BEFORE publishing
        __syncthreads();

        if (tid == 0) {
            __threadfence();
            const unsigned gen = *(volatile unsigned*)&g_gen[dir];
            const unsigned old = atomicAdd(&g_count[dir], 1);
            if (old == NCTA - 1) {
                atomicExch(&g_count[dir], 0);
                __threadfence();
                atomicAdd(&g_gen[dir], 1);
            } else {
                while (*(volatile unsigned*)&g_gen[dir] == gen) { }
            }
            __threadfence();
        }
        __syncthreads();
    }
}

// ---------------------------------------------------------------------------
extern "C" void kernel_launch(void* const* d_in, const int* in_sizes, int n_in,
                              void* d_out, int out_size)
{
    const float* x   = (const float*)d_in[0];
    const float* Wfw = (const float*)d_in[1];
    const float* bfw = (const float*)d_in[2];
    const float* Wbw = (const float*)d_in[3];
    const float* bbw = (const float*)d_in[4];
    float* out = (float*)d_out;

    dim3 g(FOURH / 128, (B_ * T_) / 128, 2);
    gemm_xp<<<g, 256>>>(x, Wfw, bfw, Wbw, bbw);

    cudaFuncSetAttribute(lstm_kernel,
                         cudaFuncAttributeMaxDynamicSharedMemorySize, SMEM_BYTES);
    lstm_kernel<<<2 * NCTA, 512, SMEM_BYTES>>>(Wfw, Wbw, out);
}